// round 4
// baseline (speedup 1.0000x reference)
#include <cuda_runtime.h>
#include <math.h>

// Problem constants
#define NMAX   100000
#define GNUM   512
#define HID    128
#define LATD   256
#define INDIM  29

// ---------------- scratch (device globals; no allocation allowed) ----------
__device__ __align__(16) float d_g  [NMAX * HID];   // (h @ W) * dis
__device__ __align__(16) float d_acc[NMAX * HID];   // edge-aggregated sum of g[src]
__device__ __align__(16) float d_h  [NMAX * HID];   // layer activations
__device__ __align__(16) float d_sums[GNUM * HID];  // pooled sums
__device__ float d_deg[NMAX];
__device__ float d_dis[NMAX];
__device__ float d_cnt[GNUM];

// ---------------- zero: acc, deg, sums, cnt --------------------------------
__global__ void k_zero(int N) {
    int i = blockIdx.x * blockDim.x + threadIdx.x;
    float4 z = make_float4(0.f, 0.f, 0.f, 0.f);
    int nacc4 = N * (HID / 4);
    if (i < nacc4) reinterpret_cast<float4*>(d_acc)[i] = z;
    if (i < N) d_deg[i] = 0.f;
    if (i < GNUM * (HID / 4)) reinterpret_cast<float4*>(d_sums)[i] = z;
    if (i < GNUM) d_cnt[i] = 0.f;
}

// ---------------- degree + inverse sqrt ------------------------------------
__global__ void k_deg(const int* __restrict__ dst, int E) {
    int i = blockIdx.x * blockDim.x + threadIdx.x;
    if (i < E) atomicAdd(&d_deg[dst[i]], 1.0f);
}

__global__ void k_dis(int N) {
    int i = blockIdx.x * blockDim.x + threadIdx.x;
    if (i < N) d_dis[i] = rsqrtf(d_deg[i] + 1.0f);
}

// ---------------- GEMM: g[n][j] = dis[n] * sum_k H[n][k] * W[k][j] ---------
// Block: 256 threads. tx = lane (4 cols), ty = warp (16 nodes).
// Covers 128 nodes x 128 cols per block. FFMA-pipe bound.
template <int K>
__global__ void __launch_bounds__(256) k_gemm(const float* __restrict__ Hin,
                                              const float* __restrict__ W,
                                              int N) {
    const float* __restrict__ Hp = (K == INDIM) ? Hin : d_h;
    int tx = threadIdx.x & 31;
    int ty = threadIdx.x >> 5;
    int node0 = blockIdx.x * 128 + ty * 16;

    float4 acc[16];
#pragma unroll
    for (int n = 0; n < 16; n++) acc[n] = make_float4(0.f, 0.f, 0.f, 0.f);

    const float4* __restrict__ W4 = reinterpret_cast<const float4*>(W);

#pragma unroll 4
    for (int k = 0; k < K; k++) {
        float4 w = W4[k * (HID / 4) + tx];
#pragma unroll
        for (int n = 0; n < 16; n++) {
            int node = min(node0 + n, N - 1);     // clamp; stores are guarded
            float a = Hp[(size_t)node * K + k];   // uniform across warp (broadcast)
            acc[n].x = fmaf(a, w.x, acc[n].x);
            acc[n].y = fmaf(a, w.y, acc[n].y);
            acc[n].z = fmaf(a, w.z, acc[n].z);
            acc[n].w = fmaf(a, w.w, acc[n].w);
        }
    }

#pragma unroll
    for (int n = 0; n < 16; n++) {
        int node = node0 + n;
        if (node < N) {
            float ds = d_dis[node];
            float4 o = make_float4(acc[n].x * ds, acc[n].y * ds,
                                   acc[n].z * ds, acc[n].w * ds);
            reinterpret_cast<float4*>(d_g)[node * (HID / 4) + tx] = o;
        }
    }
}

// ---------------- edge scatter: acc[dst] += g[src] -------------------------
// One warp per edge: 32 lanes x float4 = full 512B row. Vector RED (f32x4).
__global__ void __launch_bounds__(256) k_scatter(const int* __restrict__ src,
                                                 const int* __restrict__ dst,
                                                 int E) {
    int t = blockIdx.x * blockDim.x + threadIdx.x;
    int w = t >> 5;
    int lane = t & 31;
    if (w >= E) return;
    int s = src[w];
    int d = dst[w];
    float4 v = reinterpret_cast<const float4*>(d_g)[s * 32 + lane];
    float* p = d_acc + ((size_t)d * HID + lane * 4);
    asm volatile("red.global.add.v4.f32 [%0], {%1,%2,%3,%4};"
                 :: "l"(p), "f"(v.x), "f"(v.y), "f"(v.z), "f"(v.w)
                 : "memory");
}

// ---------------- epilogue: h = relu((acc+g)*dis + b); optionally re-zero acc
__global__ void __launch_bounds__(256) k_epi(const float* __restrict__ b,
                                             int N, int zero_acc) {
    int i = blockIdx.x * blockDim.x + threadIdx.x;
    if (i >= N * (HID / 4)) return;
    int node = i >> 5;
    int c = i & 31;
    float4 a = reinterpret_cast<float4*>(d_acc)[i];
    float4 g = reinterpret_cast<const float4*>(d_g)[i];
    float ds = d_dis[node];
    float4 bb = reinterpret_cast<const float4*>(b)[c];
    float4 o;
    o.x = fmaxf(fmaf(a.x + g.x, ds, bb.x), 0.f);
    o.y = fmaxf(fmaf(a.y + g.y, ds, bb.y), 0.f);
    o.z = fmaxf(fmaf(a.z + g.z, ds, bb.z), 0.f);
    o.w = fmaxf(fmaf(a.w + g.w, ds, bb.w), 0.f);
    reinterpret_cast<float4*>(d_h)[i] = o;
    if (zero_acc)
        reinterpret_cast<float4*>(d_acc)[i] = make_float4(0.f, 0.f, 0.f, 0.f);
}

// ---------------- mean-pool scatter: sums[batch[n]] += h[n]; cnt[b] += 1 ---
__global__ void __launch_bounds__(256) k_pool(const int* __restrict__ batch,
                                              int N) {
    int t = blockIdx.x * blockDim.x + threadIdx.x;
    int w = t >> 5;
    int lane = t & 31;
    if (w >= N) return;
    int b = batch[w];
    float4 v = reinterpret_cast<const float4*>(d_h)[w * 32 + lane];
    float* p = d_sums + b * HID + lane * 4;
    asm volatile("red.global.add.v4.f32 [%0], {%1,%2,%3,%4};"
                 :: "l"(p), "f"(v.x), "f"(v.y), "f"(v.z), "f"(v.w)
                 : "memory");
    if (lane == 0) atomicAdd(&d_cnt[b], 1.0f);
}

// ---------------- heads: mu = pooled@Wmu+bmu ; logvar = pooled@Wlv+blv -----
__global__ void __launch_bounds__(256) k_final(const float* __restrict__ Wmu,
                                               const float* __restrict__ bmu,
                                               const float* __restrict__ Wlv,
                                               const float* __restrict__ blv,
                                               float* __restrict__ out) {
    __shared__ float p[HID];
    int g = blockIdx.x;
    int j = threadIdx.x;   // 0..255
    if (j < HID) {
        float c = d_cnt[g];
        p[j] = d_sums[g * HID + j] / fmaxf(c, 1.0f);
    }
    __syncthreads();
    float mu = bmu[j];
    float lv = blv[j];
#pragma unroll 8
    for (int k = 0; k < HID; k++) {
        float pk = p[k];
        mu = fmaf(pk, Wmu[k * LATD + j], mu);
        lv = fmaf(pk, Wlv[k * LATD + j], lv);
    }
    out[g * LATD + j] = mu;
    out[GNUM * LATD + g * LATD + j] = lv;
}

// ---------------------------------------------------------------------------
extern "C" void kernel_launch(void* const* d_in, const int* in_sizes, int n_in,
                              void* d_out, int out_size) {
    const float* x     = (const float*)d_in[0];
    const int*   eidx  = (const int*)d_in[1];    // int32: JAX x64 disabled
    const int*   batch = (const int*)d_in[2];    // int32
    const float* W1  = (const float*)d_in[3];
    const float* b1  = (const float*)d_in[4];
    const float* W2  = (const float*)d_in[5];
    const float* b2  = (const float*)d_in[6];
    const float* W3  = (const float*)d_in[7];
    const float* b3  = (const float*)d_in[8];
    const float* Wmu = (const float*)d_in[9];
    const float* bmu = (const float*)d_in[10];
    const float* Wlv = (const float*)d_in[11];
    const float* blv = (const float*)d_in[12];
    float* out = (float*)d_out;

    const int N = in_sizes[2];         // 100000 (batch vector length)
    const int E = in_sizes[1] / 2;     // 3200000
    const int* src = eidx;             // edge_index[0]
    const int* dst = eidx + E;         // edge_index[1]

    const int TB = 256;
    int nb_gemm    = (N + 127) / 128;
    int nb_vec     = (N * (HID / 4) + TB - 1) / TB;   // N*32 threads
    int nb_edge    = (E + TB - 1) / TB;
    int nb_ewarp   = (E + (TB / 32) - 1) / (TB / 32); // one warp per edge
    int nb_nwarp   = (N + (TB / 32) - 1) / (TB / 32); // one warp per node
    int nb_node    = (N + TB - 1) / TB;

    // prep
    k_zero<<<nb_vec, TB>>>(N);
    k_deg <<<nb_edge, TB>>>(dst, E);
    k_dis <<<nb_node, TB>>>(N);

    // layer 1 (x: [N,29])
    k_gemm<INDIM><<<nb_gemm, TB>>>(x, W1, N);
    k_scatter<<<nb_ewarp, TB>>>(src, dst, E);
    k_epi<<<nb_vec, TB>>>(b1, N, 1);

    // layer 2
    k_gemm<HID><<<nb_gemm, TB>>>(nullptr, W2, N);
    k_scatter<<<nb_ewarp, TB>>>(src, dst, E);
    k_epi<<<nb_vec, TB>>>(b2, N, 1);

    // layer 3 (no need to re-zero acc afterwards)
    k_gemm<HID><<<nb_gemm, TB>>>(nullptr, W3, N);
    k_scatter<<<nb_ewarp, TB>>>(src, dst, E);
    k_epi<<<nb_vec, TB>>>(b3, N, 0);

    // mean pool + heads
    k_pool<<<nb_nwarp, TB>>>(batch, N);
    k_final<<<GNUM, 256>>>(Wmu, bmu, Wlv, blv, out);
}

// round 5
// speedup vs baseline: 2.1866x; 2.1866x over previous
#include <cuda_runtime.h>
#include <math.h>

// Problem constants
#define NMAX   100000
#define EMAX   3200000
#define GNUM   512
#define HID    128
#define LATD   256
#define INDIM  29

// ---------------- scratch (device globals; no allocation allowed) ----------
__device__ __align__(16) float d_g  [NMAX * HID];   // (h @ W) * dis
__device__ __align__(16) float d_h  [NMAX * HID];   // layer activations
__device__ __align__(16) float d_sums[GNUM * HID];  // pooled sums
__device__ float d_dis[NMAX];
__device__ float d_cnt[GNUM];
__device__ int   d_hist  [NMAX];                    // in-degree histogram
__device__ int   d_rowptr[NMAX + 1];                // CSR row pointer (by dst)
__device__ int   d_cursor[NMAX];                    // placement cursors
__device__ int   d_srt   [EMAX];                    // src ids grouped by dst

// ---- f32x2 packed math (sm_100+) ------------------------------------------
#define PACK2(out, lo, hi) \
    asm("mov.b64 %0, {%1, %2};" : "=l"(out) : "f"(lo), "f"(hi))
#define FMA2(d, a, b, c) \
    asm("fma.rn.f32x2 %0, %1, %2, %3;" : "=l"(d) : "l"(a), "l"(b), "l"(c))
#define UNPACK2(lo, hi, in) \
    asm("mov.b64 {%0, %1}, %2;" : "=f"(lo), "=f"(hi) : "l"(in))

// ---------------- zero: hist, sums, cnt ------------------------------------
__global__ void k_zero(int N) {
    int i = blockIdx.x * blockDim.x + threadIdx.x;
    if (i < N) d_hist[i] = 0;
    if (i < GNUM * (HID / 4))
        reinterpret_cast<float4*>(d_sums)[i] = make_float4(0.f, 0.f, 0.f, 0.f);
    if (i < GNUM) d_cnt[i] = 0.f;
}

// ---------------- in-degree histogram --------------------------------------
__global__ void k_hist(const int* __restrict__ dst, int E) {
    int i = blockIdx.x * blockDim.x + threadIdx.x;
    if (i < E) atomicAdd(&d_hist[dst[i]], 1);
}

// ---------------- single-block prefix scan + dis ---------------------------
__global__ void __launch_bounds__(1024) k_scan(int N) {
    __shared__ int wsum[32];
    __shared__ int carry;
    int tid = threadIdx.x, lane = tid & 31, wid = tid >> 5;
    if (tid == 0) carry = 0;
    __syncthreads();
    for (int base = 0; base < N; base += 1024) {
        int i = base + tid;
        int x = (i < N) ? d_hist[i] : 0;
        int v = x;
#pragma unroll
        for (int o = 1; o < 32; o <<= 1) {
            int t = __shfl_up_sync(0xffffffffu, v, o);
            if (lane >= o) v += t;
        }
        if (lane == 31) wsum[wid] = v;
        __syncthreads();
        if (wid == 0) {
            int s = wsum[lane];
#pragma unroll
            for (int o = 1; o < 32; o <<= 1) {
                int t = __shfl_up_sync(0xffffffffu, s, o);
                if (lane >= o) s += t;
            }
            wsum[lane] = s;
        }
        __syncthreads();
        int excl = carry + (wid ? wsum[wid - 1] : 0) + (v - x);
        if (i < N) {
            d_rowptr[i] = excl;
            d_cursor[i] = excl;
            d_dis[i]    = rsqrtf((float)x + 1.0f);
        }
        __syncthreads();                 // all reads of carry/wsum done
        if (tid == 0) carry += wsum[31];
        __syncthreads();
    }
    if (tid == 0) d_rowptr[N] = carry;
}

// ---------------- CSR placement: bucket src by dst -------------------------
__global__ void k_place(const int* __restrict__ src, const int* __restrict__ dst,
                        int E) {
    int i = blockIdx.x * blockDim.x + threadIdx.x;
    if (i >= E) return;
    int pos = atomicAdd(&d_cursor[dst[i]], 1);
    d_srt[pos] = src[i];
}

// ---------------- GEMM K=29: g = dis * (x @ W1) ----------------------------
template <int K>
__global__ void __launch_bounds__(256) k_gemm(const float* __restrict__ Hp,
                                              const float* __restrict__ W,
                                              int N) {
    int tx = threadIdx.x & 31;
    int ty = threadIdx.x >> 5;
    int node0 = blockIdx.x * 128 + ty * 16;

    float4 acc[16];
#pragma unroll
    for (int n = 0; n < 16; n++) acc[n] = make_float4(0.f, 0.f, 0.f, 0.f);

    const float4* __restrict__ W4 = reinterpret_cast<const float4*>(W);

#pragma unroll 4
    for (int k = 0; k < K; k++) {
        float4 w = W4[k * (HID / 4) + tx];
#pragma unroll
        for (int n = 0; n < 16; n++) {
            int node = min(node0 + n, N - 1);
            float a = Hp[(size_t)node * K + k];
            acc[n].x = fmaf(a, w.x, acc[n].x);
            acc[n].y = fmaf(a, w.y, acc[n].y);
            acc[n].z = fmaf(a, w.z, acc[n].z);
            acc[n].w = fmaf(a, w.w, acc[n].w);
        }
    }
#pragma unroll
    for (int n = 0; n < 16; n++) {
        int node = node0 + n;
        if (node < N) {
            float ds = d_dis[node];
            reinterpret_cast<float4*>(d_g)[node * (HID / 4) + tx] =
                make_float4(acc[n].x * ds, acc[n].y * ds,
                            acc[n].z * ds, acc[n].w * ds);
        }
    }
}

// ---------------- GEMM K=128: g = dis * (h @ W), f32x2 packed --------------
// 8 nodes x 4 cols per thread, 64 nodes x 128 cols per block.
__global__ void __launch_bounds__(256) k_gemm128(const float* __restrict__ W,
                                                 int N) {
    int tx = threadIdx.x & 31;
    int ty = threadIdx.x >> 5;
    int node0 = blockIdx.x * 64 + ty * 8;

    unsigned long long acc01[8], acc23[8];
    unsigned long long zero;
    PACK2(zero, 0.0f, 0.0f);
#pragma unroll
    for (int n = 0; n < 8; n++) { acc01[n] = zero; acc23[n] = zero; }

    const float4* __restrict__ W4 = reinterpret_cast<const float4*>(W);
    const float4* __restrict__ H4 = reinterpret_cast<const float4*>(d_h);

    for (int k4 = 0; k4 < HID / 4; k4++) {
        float4 a[8];
#pragma unroll
        for (int n = 0; n < 8; n++) {
            int node = min(node0 + n, N - 1);
            a[n] = H4[node * (HID / 4) + k4];
        }
#pragma unroll
        for (int kk = 0; kk < 4; kk++) {
            float4 w = W4[(k4 * 4 + kk) * (HID / 4) + tx];
            unsigned long long wxy, wzw;
            PACK2(wxy, w.x, w.y);
            PACK2(wzw, w.z, w.w);
#pragma unroll
            for (int n = 0; n < 8; n++) {
                float av = (kk == 0) ? a[n].x : (kk == 1) ? a[n].y
                         : (kk == 2) ? a[n].z : a[n].w;
                unsigned long long aa;
                PACK2(aa, av, av);
                FMA2(acc01[n], aa, wxy, acc01[n]);
                FMA2(acc23[n], aa, wzw, acc23[n]);
            }
        }
    }
#pragma unroll
    for (int n = 0; n < 8; n++) {
        int node = node0 + n;
        if (node < N) {
            float ds = d_dis[node];
            float4 o;
            UNPACK2(o.x, o.y, acc01[n]);
            UNPACK2(o.z, o.w, acc23[n]);
            o.x *= ds; o.y *= ds; o.z *= ds; o.w *= ds;
            reinterpret_cast<float4*>(d_g)[node * (HID / 4) + tx] = o;
        }
    }
}

// ---------------- CSR gather + fused epilogue ------------------------------
// One warp per dst node; lane owns 4 cols. h[d] = relu((sum_src g + g[d])*dis + b)
__device__ __forceinline__ float4 gather_row(int d, int lane) {
    const float4* __restrict__ G4 = reinterpret_cast<const float4*>(d_g);
    int beg = d_rowptr[d];
    int end = d_rowptr[d + 1];
    float4 v = make_float4(0.f, 0.f, 0.f, 0.f);
    int e = beg;
    for (; e + 4 <= end; e += 4) {
        int s0 = d_srt[e], s1 = d_srt[e + 1], s2 = d_srt[e + 2], s3 = d_srt[e + 3];
        float4 a0 = G4[s0 * (HID / 4) + lane];
        float4 a1 = G4[s1 * (HID / 4) + lane];
        float4 a2 = G4[s2 * (HID / 4) + lane];
        float4 a3 = G4[s3 * (HID / 4) + lane];
        v.x += (a0.x + a1.x) + (a2.x + a3.x);
        v.y += (a0.y + a1.y) + (a2.y + a3.y);
        v.z += (a0.z + a1.z) + (a2.z + a3.z);
        v.w += (a0.w + a1.w) + (a2.w + a3.w);
    }
    for (; e < end; e++) {
        float4 a = G4[d_srt[e] * (HID / 4) + lane];
        v.x += a.x; v.y += a.y; v.z += a.z; v.w += a.w;
    }
    float4 g = G4[d * (HID / 4) + lane];
    v.x += g.x; v.y += g.y; v.z += g.z; v.w += g.w;
    return v;
}

__global__ void __launch_bounds__(256) k_gather(const float* __restrict__ b,
                                                int N) {
    int t = blockIdx.x * blockDim.x + threadIdx.x;
    int d = t >> 5, lane = t & 31;
    if (d >= N) return;
    float4 v = gather_row(d, lane);
    float ds = d_dis[d];
    float4 bb = reinterpret_cast<const float4*>(b)[lane];
    float4 o;
    o.x = fmaxf(fmaf(v.x, ds, bb.x), 0.f);
    o.y = fmaxf(fmaf(v.y, ds, bb.y), 0.f);
    o.z = fmaxf(fmaf(v.z, ds, bb.z), 0.f);
    o.w = fmaxf(fmaf(v.w, ds, bb.w), 0.f);
    reinterpret_cast<float4*>(d_h)[d * (HID / 4) + lane] = o;
}

// layer 3: fused epilogue + mean-pool RED (no d_h write, no pool pass)
__global__ void __launch_bounds__(256) k_gather_pool(const float* __restrict__ b,
                                                     const int* __restrict__ batch,
                                                     int N) {
    int t = blockIdx.x * blockDim.x + threadIdx.x;
    int d = t >> 5, lane = t & 31;
    if (d >= N) return;
    float4 v = gather_row(d, lane);
    float ds = d_dis[d];
    float4 bb = reinterpret_cast<const float4*>(b)[lane];
    float4 o;
    o.x = fmaxf(fmaf(v.x, ds, bb.x), 0.f);
    o.y = fmaxf(fmaf(v.y, ds, bb.y), 0.f);
    o.z = fmaxf(fmaf(v.z, ds, bb.z), 0.f);
    o.w = fmaxf(fmaf(v.w, ds, bb.w), 0.f);
    int g = batch[d];
    float* p = d_sums + g * HID + lane * 4;
    asm volatile("red.global.add.v4.f32 [%0], {%1,%2,%3,%4};"
                 :: "l"(p), "f"(o.x), "f"(o.y), "f"(o.z), "f"(o.w)
                 : "memory");
    if (lane == 0) atomicAdd(&d_cnt[g], 1.0f);
}

// ---------------- heads ----------------------------------------------------
__global__ void __launch_bounds__(256) k_final(const float* __restrict__ Wmu,
                                               const float* __restrict__ bmu,
                                               const float* __restrict__ Wlv,
                                               const float* __restrict__ blv,
                                               float* __restrict__ out) {
    __shared__ float p[HID];
    int g = blockIdx.x;
    int j = threadIdx.x;
    if (j < HID) {
        float c = d_cnt[g];
        p[j] = d_sums[g * HID + j] / fmaxf(c, 1.0f);
    }
    __syncthreads();
    float mu = bmu[j];
    float lv = blv[j];
#pragma unroll 8
    for (int k = 0; k < HID; k++) {
        float pk = p[k];
        mu = fmaf(pk, Wmu[k * LATD + j], mu);
        lv = fmaf(pk, Wlv[k * LATD + j], lv);
    }
    out[g * LATD + j] = mu;
    out[GNUM * LATD + g * LATD + j] = lv;
}

// ---------------------------------------------------------------------------
extern "C" void kernel_launch(void* const* d_in, const int* in_sizes, int n_in,
                              void* d_out, int out_size) {
    const float* x     = (const float*)d_in[0];
    const int*   eidx  = (const int*)d_in[1];    // int32 (JAX x64 disabled)
    const int*   batch = (const int*)d_in[2];
    const float* W1  = (const float*)d_in[3];
    const float* b1  = (const float*)d_in[4];
    const float* W2  = (const float*)d_in[5];
    const float* b2  = (const float*)d_in[6];
    const float* W3  = (const float*)d_in[7];
    const float* b3  = (const float*)d_in[8];
    const float* Wmu = (const float*)d_in[9];
    const float* bmu = (const float*)d_in[10];
    const float* Wlv = (const float*)d_in[11];
    const float* blv = (const float*)d_in[12];
    float* out = (float*)d_out;

    const int N = in_sizes[2];       // 100000
    const int E = in_sizes[1] / 2;   // 3200000
    const int* src = eidx;
    const int* dst = eidx + E;

    const int TB = 256;
    int nb_zero  = (N + TB - 1) / TB;
    int nb_edge  = (E + TB - 1) / TB;
    int nb_gemm  = (N + 127) / 128;
    int nb_g128  = (N + 63) / 64;
    int nb_nwarp = (N + (TB / 32) - 1) / (TB / 32);

    // CSR build (by dst) + degree
    k_zero <<<nb_zero, TB>>>(N);
    k_hist <<<nb_edge, TB>>>(dst, E);
    k_scan <<<1, 1024>>>(N);
    k_place<<<nb_edge, TB>>>(src, dst, E);

    // layer 1
    k_gemm<INDIM><<<nb_gemm, TB>>>(x, W1, N);
    k_gather<<<nb_nwarp, TB>>>(b1, N);

    // layer 2
    k_gemm128<<<nb_g128, TB>>>(W2, N);
    k_gather<<<nb_nwarp, TB>>>(b2, N);

    // layer 3 (fused pool)
    k_gemm128<<<nb_g128, TB>>>(W3, N);
    k_gather_pool<<<nb_nwarp, TB>>>(b3, batch, N);

    // heads
    k_final<<<GNUM, 256>>>(Wmu, bmu, Wlv, blv, out);
}

// round 6
// speedup vs baseline: 2.7608x; 1.2626x over previous
#include <cuda_runtime.h>
#include <cuda_fp16.h>
#include <math.h>

// Problem constants
#define NMAX   100000
#define EMAX   3200000
#define GNUM   512
#define HID    128
#define LATD   256
#define INDIM  29

// ---------------- scratch (device globals; no allocation allowed) ----------
__device__ __align__(16) __half d_g [NMAX * HID];   // fp16 messages: (h@W)*dis
__device__ __align__(16) float  d_h [NMAX * HID];   // layer activations (fp32)
__device__ __align__(16) float  d_sums[GNUM * HID]; // pooled sums
__device__ float d_dis[NMAX];
__device__ float d_cnt[GNUM];
__device__ int   d_hist  [NMAX];                    // in-degree histogram
__device__ int   d_rowptr[NMAX + 1];                // CSR row pointer (by dst)
__device__ int   d_cursor[NMAX];                    // placement cursors
__device__ int   d_srt   [EMAX];                    // src ids grouped by dst
__device__ int   d_part  [128];                     // scan partials

struct h4 { __half2 a, b; };                        // 8-byte packed 4x fp16

// ---- f32x2 packed math (sm_100+) ------------------------------------------
#define PACK2(out, lo, hi) \
    asm("mov.b64 %0, {%1, %2};" : "=l"(out) : "f"(lo), "f"(hi))
#define FMA2(d, a, b, c) \
    asm("fma.rn.f32x2 %0, %1, %2, %3;" : "=l"(d) : "l"(a), "l"(b), "l"(c))
#define UNPACK2(lo, hi, in) \
    asm("mov.b64 {%0, %1}, %2;" : "=f"(lo), "=f"(hi) : "l"(in))

// ---------------- zero: hist, sums, cnt ------------------------------------
__global__ void k_zero(int N) {
    int i = blockIdx.x * blockDim.x + threadIdx.x;
    if (i < N) d_hist[i] = 0;
    if (i < GNUM * (HID / 4))
        reinterpret_cast<float4*>(d_sums)[i] = make_float4(0.f, 0.f, 0.f, 0.f);
    if (i < GNUM) d_cnt[i] = 0.f;
}

// ---------------- in-degree histogram (4 edges/thread) ---------------------
__global__ void k_hist(const int* __restrict__ dst, int E) {
    int i = (blockIdx.x * blockDim.x + threadIdx.x) * 4;
    if (i + 4 <= E) {
        int4 d = *reinterpret_cast<const int4*>(dst + i);
        atomicAdd(&d_hist[d.x], 1);
        atomicAdd(&d_hist[d.y], 1);
        atomicAdd(&d_hist[d.z], 1);
        atomicAdd(&d_hist[d.w], 1);
    } else {
        for (int e = i; e < E; e++) atomicAdd(&d_hist[dst[e]], 1);
    }
}

// ---------------- 3-pass parallel scan --------------------------------------
__global__ void __launch_bounds__(1024) k_scanA(int N) {
    __shared__ int s[32];
    int tid = threadIdx.x, lane = tid & 31, wid = tid >> 5;
    int i = blockIdx.x * 1024 + tid;
    int x = (i < N) ? d_hist[i] : 0;
#pragma unroll
    for (int o = 16; o; o >>= 1) x += __shfl_down_sync(0xffffffffu, x, o);
    if (lane == 0) s[wid] = x;
    __syncthreads();
    if (wid == 0) {
        int v = s[lane];
#pragma unroll
        for (int o = 16; o; o >>= 1) v += __shfl_down_sync(0xffffffffu, v, o);
        if (lane == 0) d_part[blockIdx.x] = v;
    }
}

__global__ void __launch_bounds__(128) k_scanB(int P, int N) {
    __shared__ int ws[4];
    int t = threadIdx.x, lane = t & 31, wid = t >> 5;
    int x = (t < P) ? d_part[t] : 0;
    int v = x;
#pragma unroll
    for (int o = 1; o < 32; o <<= 1) {
        int u = __shfl_up_sync(0xffffffffu, v, o);
        if (lane >= o) v += u;
    }
    if (lane == 31) ws[wid] = v;
    __syncthreads();
    int off = 0;
    for (int w = 0; w < wid; w++) off += ws[w];
    v += off;
    if (t < P) d_part[t] = v - x;        // exclusive
    if (t == P - 1) d_rowptr[N] = v;     // total
}

__global__ void __launch_bounds__(1024) k_scanC(int N) {
    __shared__ int wsum[32];
    int tid = threadIdx.x, lane = tid & 31, wid = tid >> 5;
    int i = blockIdx.x * 1024 + tid;
    int x = (i < N) ? d_hist[i] : 0;
    int v = x;
#pragma unroll
    for (int o = 1; o < 32; o <<= 1) {
        int u = __shfl_up_sync(0xffffffffu, v, o);
        if (lane >= o) v += u;
    }
    if (lane == 31) wsum[wid] = v;
    __syncthreads();
    if (wid == 0) {
        int s = wsum[lane];
#pragma unroll
        for (int o = 1; o < 32; o <<= 1) {
            int u = __shfl_up_sync(0xffffffffu, s, o);
            if (lane >= o) s += u;
        }
        wsum[lane] = s;
    }
    __syncthreads();
    if (i < N) {
        int excl = d_part[blockIdx.x] + (wid ? wsum[wid - 1] : 0) + (v - x);
        d_rowptr[i] = excl;
        d_cursor[i] = excl;
        d_dis[i]    = rsqrtf((float)x + 1.0f);
    }
}

// ---------------- CSR placement: bucket src by dst (4 edges/thread) --------
__global__ void k_place(const int* __restrict__ src, const int* __restrict__ dst,
                        int E) {
    int i = (blockIdx.x * blockDim.x + threadIdx.x) * 4;
    if (i + 4 <= E) {
        int4 s = *reinterpret_cast<const int4*>(src + i);
        int4 d = *reinterpret_cast<const int4*>(dst + i);
        d_srt[atomicAdd(&d_cursor[d.x], 1)] = s.x;
        d_srt[atomicAdd(&d_cursor[d.y], 1)] = s.y;
        d_srt[atomicAdd(&d_cursor[d.z], 1)] = s.z;
        d_srt[atomicAdd(&d_cursor[d.w], 1)] = s.w;
    } else {
        for (int e = i; e < E; e++)
            d_srt[atomicAdd(&d_cursor[dst[e]], 1)] = src[e];
    }
}

// ---------------- store helper: float4 -> packed 4x fp16 -------------------
__device__ __forceinline__ void store_g(int node, int tx, float4 o) {
    h4 p;
    p.a = __floats2half2_rn(o.x, o.y);
    p.b = __floats2half2_rn(o.z, o.w);
    reinterpret_cast<h4*>(d_g)[node * 32 + tx] = p;
}

// ---------------- GEMM K=29: g = dis * (x @ W1) ----------------------------
template <int K>
__global__ void __launch_bounds__(256) k_gemm(const float* __restrict__ Hp,
                                              const float* __restrict__ W,
                                              int N) {
    int tx = threadIdx.x & 31;
    int ty = threadIdx.x >> 5;
    int node0 = blockIdx.x * 128 + ty * 16;

    float4 acc[16];
#pragma unroll
    for (int n = 0; n < 16; n++) acc[n] = make_float4(0.f, 0.f, 0.f, 0.f);

    const float4* __restrict__ W4 = reinterpret_cast<const float4*>(W);

#pragma unroll 4
    for (int k = 0; k < K; k++) {
        float4 w = W4[k * (HID / 4) + tx];
#pragma unroll
        for (int n = 0; n < 16; n++) {
            int node = min(node0 + n, N - 1);
            float a = Hp[(size_t)node * K + k];
            acc[n].x = fmaf(a, w.x, acc[n].x);
            acc[n].y = fmaf(a, w.y, acc[n].y);
            acc[n].z = fmaf(a, w.z, acc[n].z);
            acc[n].w = fmaf(a, w.w, acc[n].w);
        }
    }
#pragma unroll
    for (int n = 0; n < 16; n++) {
        int node = node0 + n;
        if (node < N) {
            float ds = d_dis[node];
            store_g(node, tx, make_float4(acc[n].x * ds, acc[n].y * ds,
                                          acc[n].z * ds, acc[n].w * ds));
        }
    }
}

// ---------------- GEMM K=128: g = dis * (h @ W), f32x2 packed --------------
__global__ void __launch_bounds__(256) k_gemm128(const float* __restrict__ W,
                                                 int N) {
    int tx = threadIdx.x & 31;
    int ty = threadIdx.x >> 5;
    int node0 = blockIdx.x * 64 + ty * 8;

    unsigned long long acc01[8], acc23[8];
    unsigned long long zero;
    PACK2(zero, 0.0f, 0.0f);
#pragma unroll
    for (int n = 0; n < 8; n++) { acc01[n] = zero; acc23[n] = zero; }

    const float4* __restrict__ W4 = reinterpret_cast<const float4*>(W);
    const float4* __restrict__ H4 = reinterpret_cast<const float4*>(d_h);

    for (int k4 = 0; k4 < HID / 4; k4++) {
        float4 a[8];
#pragma unroll
        for (int n = 0; n < 8; n++) {
            int node = min(node0 + n, N - 1);
            a[n] = H4[node * (HID / 4) + k4];
        }
#pragma unroll
        for (int kk = 0; kk < 4; kk++) {
            float4 w = W4[(k4 * 4 + kk) * (HID / 4) + tx];
            unsigned long long wxy, wzw;
            PACK2(wxy, w.x, w.y);
            PACK2(wzw, w.z, w.w);
#pragma unroll
            for (int n = 0; n < 8; n++) {
                float av = (kk == 0) ? a[n].x : (kk == 1) ? a[n].y
                         : (kk == 2) ? a[n].z : a[n].w;
                unsigned long long aa;
                PACK2(aa, av, av);
                FMA2(acc01[n], aa, wxy, acc01[n]);
                FMA2(acc23[n], aa, wzw, acc23[n]);
            }
        }
    }
#pragma unroll
    for (int n = 0; n < 8; n++) {
        int node = node0 + n;
        if (node < N) {
            float ds = d_dis[node];
            float4 o;
            UNPACK2(o.x, o.y, acc01[n]);
            UNPACK2(o.z, o.w, acc23[n]);
            o.x *= ds; o.y *= ds; o.z *= ds; o.w *= ds;
            store_g(node, tx, o);
        }
    }
}

// ---------------- CSR gather + fused epilogue ------------------------------
// One warp per dst node; lane owns 4 cols (8B fp16). Accumulate fp32.
__device__ __forceinline__ void addh4(float4& v, h4 p) {
    float2 f0 = __half22float2(p.a);
    float2 f1 = __half22float2(p.b);
    v.x += f0.x; v.y += f0.y; v.z += f1.x; v.w += f1.y;
}

__device__ __forceinline__ float4 gather_row(int d, int lane) {
    const h4* __restrict__ G = reinterpret_cast<const h4*>(d_g);
    int beg = d_rowptr[d];
    int end = d_rowptr[d + 1];
    float4 v = make_float4(0.f, 0.f, 0.f, 0.f);
    int e = beg;
    for (; e + 4 <= end; e += 4) {
        int s0 = d_srt[e], s1 = d_srt[e + 1], s2 = d_srt[e + 2], s3 = d_srt[e + 3];
        h4 a0 = G[s0 * 32 + lane];
        h4 a1 = G[s1 * 32 + lane];
        h4 a2 = G[s2 * 32 + lane];
        h4 a3 = G[s3 * 32 + lane];
        addh4(v, a0); addh4(v, a1); addh4(v, a2); addh4(v, a3);
    }
    for (; e < end; e++) addh4(v, G[d_srt[e] * 32 + lane]);
    addh4(v, G[d * 32 + lane]);          // self loop
    return v;
}

__global__ void __launch_bounds__(256) k_gather(const float* __restrict__ b,
                                                int N) {
    int t = blockIdx.x * blockDim.x + threadIdx.x;
    int d = t >> 5, lane = t & 31;
    if (d >= N) return;
    float4 v = gather_row(d, lane);
    float ds = d_dis[d];
    float4 bb = reinterpret_cast<const float4*>(b)[lane];
    float4 o;
    o.x = fmaxf(fmaf(v.x, ds, bb.x), 0.f);
    o.y = fmaxf(fmaf(v.y, ds, bb.y), 0.f);
    o.z = fmaxf(fmaf(v.z, ds, bb.z), 0.f);
    o.w = fmaxf(fmaf(v.w, ds, bb.w), 0.f);
    reinterpret_cast<float4*>(d_h)[d * (HID / 4) + lane] = o;
}

// layer 3: fused epilogue + mean-pool RED
__global__ void __launch_bounds__(256) k_gather_pool(const float* __restrict__ b,
                                                     const int* __restrict__ batch,
                                                     int N) {
    int t = blockIdx.x * blockDim.x + threadIdx.x;
    int d = t >> 5, lane = t & 31;
    if (d >= N) return;
    float4 v = gather_row(d, lane);
    float ds = d_dis[d];
    float4 bb = reinterpret_cast<const float4*>(b)[lane];
    float4 o;
    o.x = fmaxf(fmaf(v.x, ds, bb.x), 0.f);
    o.y = fmaxf(fmaf(v.y, ds, bb.y), 0.f);
    o.z = fmaxf(fmaf(v.z, ds, bb.z), 0.f);
    o.w = fmaxf(fmaf(v.w, ds, bb.w), 0.f);
    int g = batch[d];
    float* p = d_sums + g * HID + lane * 4;
    asm volatile("red.global.add.v4.f32 [%0], {%1,%2,%3,%4};"
                 :: "l"(p), "f"(o.x), "f"(o.y), "f"(o.z), "f"(o.w)
                 : "memory");
    if (lane == 0) atomicAdd(&d_cnt[g], 1.0f);
}

// ---------------- heads ----------------------------------------------------
__global__ void __launch_bounds__(256) k_final(const float* __restrict__ Wmu,
                                               const float* __restrict__ bmu,
                                               const float* __restrict__ Wlv,
                                               const float* __restrict__ blv,
                                               float* __restrict__ out) {
    __shared__ float p[HID];
    int g = blockIdx.x;
    int j = threadIdx.x;
    if (j < HID) {
        float c = d_cnt[g];
        p[j] = d_sums[g * HID + j] / fmaxf(c, 1.0f);
    }
    __syncthreads();
    float mu = bmu[j];
    float lv = blv[j];
#pragma unroll 8
    for (int k = 0; k < HID; k++) {
        float pk = p[k];
        mu = fmaf(pk, Wmu[k * LATD + j], mu);
        lv = fmaf(pk, Wlv[k * LATD + j], lv);
    }
    out[g * LATD + j] = mu;
    out[GNUM * LATD + g * LATD + j] = lv;
}

// ---------------------------------------------------------------------------
extern "C" void kernel_launch(void* const* d_in, const int* in_sizes, int n_in,
                              void* d_out, int out_size) {
    const float* x     = (const float*)d_in[0];
    const int*   eidx  = (const int*)d_in[1];    // int32 (JAX x64 disabled)
    const int*   batch = (const int*)d_in[2];
    const float* W1  = (const float*)d_in[3];
    const float* b1  = (const float*)d_in[4];
    const float* W2  = (const float*)d_in[5];
    const float* b2  = (const float*)d_in[6];
    const float* W3  = (const float*)d_in[7];
    const float* b3  = (const float*)d_in[8];
    const float* Wmu = (const float*)d_in[9];
    const float* bmu = (const float*)d_in[10];
    const float* Wlv = (const float*)d_in[11];
    const float* blv = (const float*)d_in[12];
    float* out = (float*)d_out;

    const int N = in_sizes[2];       // 100000
    const int E = in_sizes[1] / 2;   // 3200000
    const int* src = eidx;
    const int* dst = eidx + E;

    const int TB = 256;
    int nb_zero  = (N + TB - 1) / TB;
    int nb_e4    = ((E + 3) / 4 + TB - 1) / TB;       // 4 edges/thread
    int nb_gemm  = (N + 127) / 128;
    int nb_g128  = (N + 63) / 64;
    int nb_nwarp = (N + (TB / 32) - 1) / (TB / 32);
    int P        = (N + 1023) / 1024;                 // scan partials (<=128)

    // CSR build (by dst) + degree
    k_zero <<<nb_zero, TB>>>(N);
    k_hist <<<nb_e4, TB>>>(dst, E);
    k_scanA<<<P, 1024>>>(N);
    k_scanB<<<1, 128>>>(P, N);
    k_scanC<<<P, 1024>>>(N);
    k_place<<<nb_e4, TB>>>(src, dst, E);

    // layer 1
    k_gemm<INDIM><<<nb_gemm, TB>>>(x, W1, N);
    k_gather<<<nb_nwarp, TB>>>(b1, N);

    // layer 2
    k_gemm128<<<nb_g128, TB>>>(W2, N);
    k_gather<<<nb_nwarp, TB>>>(b2, N);

    // layer 3 (fused pool)
    k_gemm128<<<nb_g128, TB>>>(W3, N);
    k_gather_pool<<<nb_nwarp, TB>>>(b3, batch, N);

    // heads
    k_final<<<GNUM, 256>>>(Wmu, bmu, Wlv, blv, out);
}